// round 10
// baseline (speedup 1.0000x reference)
#include <cuda_runtime.h>
#include <cuda_fp16.h>
#include <cstdint>

#define DIM 128
#define NODES_MAX 50304
#define EDGES_MAX 1700000
#define SCAN_B 1024
#define SCAN_NBLK 50

typedef unsigned long long ull;

// ---------------- scratch (static device globals) --------------------------
__device__ __align__(16) float  g_z[NODES_MAX * DIM];   // z2 fp32 (GEMM2 out)
__device__ __align__(16) __half g_h2[NODES_MAX * DIM];  // h fp16 (gather reads)
__device__ __align__(16) __half g_zh[NODES_MAX * DIM];  // z fp16 (gather out / GEMM1 A)
__device__ __align__(16) __half g_yh[NODES_MAX * DIM];  // y fp16 (GEMM1 out / GEMM2 A)
__device__ __align__(16) __half g_w1h[DIM * DIM];       // W1 fp16 (K-major, as-is)
__device__ __align__(16) __half g_w2h[DIM * DIM];       // W2 fp16
__device__ float g_sum[DIM];
__device__ float g_sq[DIM];
__device__ int g_deg[NODES_MAX];
__device__ int g_off[NODES_MAX];
__device__ int g_cur[NODES_MAX];
__device__ int g_elist[EDGES_MAX];
__device__ volatile int g_sstat[SCAN_NBLK];
__device__ volatile int g_sagg[SCAN_NBLK];
__device__ volatile int g_spre[SCAN_NBLK];

// ---------------- mma.sync helpers (base ISA, runs on tensor cores) --------
__device__ __forceinline__ uint32_t smem_u32(const void* p) {
    uint32_t a;
    asm("{ .reg .u64 t; cvta.to.shared.u64 t, %1; cvt.u32.u64 %0, t; }"
        : "=r"(a) : "l"(p));
    return a;
}
__device__ __forceinline__ void ldsm4(uint32_t* r, uint32_t addr) {
    asm volatile("ldmatrix.sync.aligned.m8n8.x4.shared.b16 {%0,%1,%2,%3}, [%4];"
                 : "=r"(r[0]), "=r"(r[1]), "=r"(r[2]), "=r"(r[3]) : "r"(addr));
}
__device__ __forceinline__ void ldsm4t(uint32_t* r, uint32_t addr) {
    asm volatile("ldmatrix.sync.aligned.m8n8.x4.trans.shared.b16 {%0,%1,%2,%3}, [%4];"
                 : "=r"(r[0]), "=r"(r[1]), "=r"(r[2]), "=r"(r[3]) : "r"(addr));
}
__device__ __forceinline__ void mma16816(float* c, const uint32_t* a,
                                         uint32_t b0, uint32_t b1) {
    asm volatile(
        "mma.sync.aligned.m16n8k16.row.col.f32.f16.f16.f32 "
        "{%0,%1,%2,%3}, {%4,%5,%6,%7}, {%8,%9}, {%0,%1,%2,%3};"
        : "+f"(c[0]), "+f"(c[1]), "+f"(c[2]), "+f"(c[3])
        : "r"(a[0]), "r"(a[1]), "r"(a[2]), "r"(a[3]), "r"(b0), "r"(b1));
}

// ---------------------------------------------------------------------------
// 0) zero degree counters, BN accumulators, scan statuses
// ---------------------------------------------------------------------------
__global__ void zero_kernel(int n) {
    int i = blockIdx.x * blockDim.x + threadIdx.x;
    if (i < n) g_deg[i] = 0;
    if (i < DIM) { g_sum[i] = 0.f; g_sq[i] = 0.f; }
    if (i < SCAN_NBLK) g_sstat[i] = 0;
}

// ---------------------------------------------------------------------------
// 1) prep: degree histogram (4 edges/thread, MLP=4) + h->fp16 + W1/W2->fp16
// ---------------------------------------------------------------------------
__global__ void prep_kernel(const int* __restrict__ dst,
                            const float* __restrict__ W1,
                            const float* __restrict__ W2,
                            const float* __restrict__ h,
                            int nnodes, int E4, int total4) {
    int i = blockIdx.x * blockDim.x + threadIdx.x;
    if (i < E4) {
        int4 d4 = ((const int4*)dst)[i];
        if ((unsigned)d4.x < (unsigned)nnodes) atomicAdd(&g_deg[d4.x], 1);
        if ((unsigned)d4.y < (unsigned)nnodes) atomicAdd(&g_deg[d4.y], 1);
        if ((unsigned)d4.z < (unsigned)nnodes) atomicAdd(&g_deg[d4.z], 1);
        if ((unsigned)d4.w < (unsigned)nnodes) atomicAdd(&g_deg[d4.w], 1);
    }
    if (i < total4) {
        float4 v = ((const float4*)h)[i];
        __half2 a = __floats2half2_rn(v.x, v.y);
        __half2 b = __floats2half2_rn(v.z, v.w);
        uint2 u;
        u.x = *(unsigned int*)&a;
        u.y = *(unsigned int*)&b;
        ((uint2*)g_h2)[i] = u;
    }
    if (i < 2 * DIM * DIM) {
        int w = i >> 14;            // 0 -> W1, 1 -> W2
        int idx = i & 16383;
        float val = w ? W2[idx] : W1[idx];
        __half hv = __float2half_rn(val);
        if (w) g_w2h[idx] = hv;
        else   g_w1h[idx] = hv;
    }
}

// ---------------------------------------------------------------------------
// 2) single-pass exclusive scan (warp-parallel decoupled lookback).
//    49 CTAs, all co-resident on 148 SMs -> spins cannot deadlock.
// ---------------------------------------------------------------------------
__global__ void scan_kernel(int n) {
    __shared__ int wsum[32];
    __shared__ int s_excl;
    int t = threadIdx.x, b = blockIdx.x;
    int i = b * SCAN_B + t;
    int d = (i < n) ? g_deg[i] : 0;
    int lane = t & 31, w = t >> 5;
    int v = d;
#pragma unroll
    for (int s = 1; s < 32; s <<= 1) {
        int u = __shfl_up_sync(0xffffffffu, v, s);
        if (lane >= s) v += u;
    }
    if (lane == 31) wsum[w] = v;
    __syncthreads();
    if (w == 0) {
        int x = wsum[lane];
#pragma unroll
        for (int s = 1; s < 32; s <<= 1) {
            int u = __shfl_up_sync(0xffffffffu, x, s);
            if (lane >= s) x += u;
        }
        wsum[lane] = x;
    }
    __syncthreads();
    int incl = v + (w ? wsum[w - 1] : 0);
    int agg = wsum[31];

    if (t == 0) {
        if (b == 0) {
            g_spre[0] = agg; __threadfence(); g_sstat[0] = 2; s_excl = 0;
        } else {
            g_sagg[b] = agg; __threadfence(); g_sstat[b] = 1;
        }
    }
    if (b > 0 && w == 0) {
        int excl = 0;
        int pos = b;
        while (pos > 0) {
            int j = pos - 1 - lane;
            int st = (j >= 0) ? g_sstat[j] : 2;
            unsigned nr = __ballot_sync(0xffffffffu, st == 0);
            unsigned dn = __ballot_sync(0xffffffffu, st == 2);
            int fd = dn ? (__ffs(dn) - 1) : 32;
            int fnr = nr ? (__ffs(nr) - 1) : 32;
            if (fd < fnr) {
                __threadfence();
                int vl = 0;
                if (j >= 0 && lane <= fd) vl = (lane == fd) ? g_spre[j] : g_sagg[j];
                int contrib = (lane <= fd) ? vl : 0;
#pragma unroll
                for (int s = 16; s > 0; s >>= 1)
                    contrib += __shfl_xor_sync(0xffffffffu, contrib, s);
                excl += contrib;
                pos = 0;
            } else if (fnr == 32) {
                __threadfence();
                int contrib = (j >= 0) ? g_sagg[j] : 0;
#pragma unroll
                for (int s = 16; s > 0; s >>= 1)
                    contrib += __shfl_xor_sync(0xffffffffu, contrib, s);
                excl += contrib;
                pos -= 32;
            }
        }
        if (lane == 0) {
            g_spre[b] = excl + agg;
            __threadfence();
            g_sstat[b] = 2;
            s_excl = excl;
        }
    }
    __syncthreads();
    if (i < n) {
        int e = incl - d + s_excl;
        g_off[i] = e;
        g_cur[i] = e;
    }
}

// ---------------------------------------------------------------------------
// 3) scatter src ids into per-dst segments (4 edges/thread, MLP=4)
// ---------------------------------------------------------------------------
__global__ void scatter_kernel(const int* __restrict__ src,
                               const int* __restrict__ dst, int nnodes, int E4) {
    int i = blockIdx.x * blockDim.x + threadIdx.x;
    if (i >= E4) return;
    int4 d4 = ((const int4*)dst)[i];
    int4 s4 = ((const int4*)src)[i];
    int p0 = -1, p1 = -1, p2 = -1, p3 = -1;
    if ((unsigned)d4.x < (unsigned)nnodes) p0 = atomicAdd(&g_cur[d4.x], 1);
    if ((unsigned)d4.y < (unsigned)nnodes) p1 = atomicAdd(&g_cur[d4.y], 1);
    if ((unsigned)d4.z < (unsigned)nnodes) p2 = atomicAdd(&g_cur[d4.z], 1);
    if ((unsigned)d4.w < (unsigned)nnodes) p3 = atomicAdd(&g_cur[d4.w], 1);
    if (p0 >= 0 && (unsigned)s4.x < (unsigned)nnodes) g_elist[p0] = s4.x;
    if (p1 >= 0 && (unsigned)s4.y < (unsigned)nnodes) g_elist[p1] = s4.y;
    if (p2 >= 0 && (unsigned)s4.z < (unsigned)nnodes) g_elist[p2] = s4.z;
    if (p3 >= 0 && (unsigned)s4.w < (unsigned)nnodes) g_elist[p3] = s4.w;
}

// ---------------------------------------------------------------------------
// 4) gather: z[u] = (1+eps)*h[u] + sum_v h_fp16[v]; writes z as fp16
// ---------------------------------------------------------------------------
__global__ void gather_kernel(const float* __restrict__ h,
                              const float* __restrict__ eps, int nnodes) {
    int warp = (blockIdx.x * blockDim.x + threadIdx.x) >> 5;
    int lane = threadIdx.x & 31;
    if (warp >= nnodes) return;
    int u = warp;
    int off = g_off[u];
    int dg = g_deg[u];

    float4 acc = make_float4(0.f, 0.f, 0.f, 0.f);
    int j = 0;
    for (; j + 32 <= dg; j += 32) {
        int vid = g_elist[off + j + lane];
#pragma unroll
        for (int k = 0; k < 32; k++) {
            int v = __shfl_sync(0xffffffffu, vid, k);
            uint2 uu = *(const uint2*)(g_h2 + (long long)v * DIM + lane * 4);
            __half2 p0 = *(__half2*)&uu.x;
            __half2 p1 = *(__half2*)&uu.y;
            float2 f0 = __half22float2(p0);
            float2 f1 = __half22float2(p1);
            acc.x += f0.x; acc.y += f0.y; acc.z += f1.x; acc.w += f1.y;
        }
    }
    int rem = dg - j;
    if (rem > 0) {
        int vid = (lane < rem) ? g_elist[off + j + lane] : 0;
        for (int k = 0; k < rem; k++) {
            int v = __shfl_sync(0xffffffffu, vid, k);
            uint2 uu = *(const uint2*)(g_h2 + (long long)v * DIM + lane * 4);
            __half2 p0 = *(__half2*)&uu.x;
            __half2 p1 = *(__half2*)&uu.y;
            float2 f0 = __half22float2(p0);
            float2 f1 = __half22float2(p1);
            acc.x += f0.x; acc.y += f0.y; acc.z += f1.x; acc.w += f1.y;
        }
    }
    float e = 1.0f + eps[0];
    float4 hv = *(const float4*)(h + (long long)u * DIM + lane * 4);
    acc.x += e * hv.x; acc.y += e * hv.y; acc.z += e * hv.z; acc.w += e * hv.w;
    __half2 o0 = __floats2half2_rn(acc.x, acc.y);
    __half2 o1 = __floats2half2_rn(acc.z, acc.w);
    uint2 ou;
    ou.x = *(unsigned int*)&o0;
    ou.y = *(unsigned int*)&o1;
    *(uint2*)(g_zh + (long long)u * DIM + lane * 4) = ou;
}

// ---------------------------------------------------------------------------
// 5/6) HMMA GEMM: 64-row x 128-col tile per 128-thread block (4 warps).
// ---------------------------------------------------------------------------
#define MMA_STRIDE 272
#define SM_A_SZ (64 * MMA_STRIDE)     // 17408
#define SM_B_OFF SM_A_SZ
#define SMEM_GEMM (SM_A_SZ + 128 * MMA_STRIDE)  // 52224

__global__ __launch_bounds__(128)
void mma_kernel(const __half* __restrict__ A, const __half* __restrict__ B,
                const float* __restrict__ bias, __half* __restrict__ outh,
                float* __restrict__ outf, int M, int mode) {
    extern __shared__ char smem[];
    __shared__ float sbias[DIM];
    __shared__ float sS[4][DIM];
    __shared__ float sQ[4][DIM];

    int tid = threadIdx.x, wid = tid >> 5, lane = tid & 31;
    int tig = lane & 3, gid = lane >> 2;
    int row0 = blockIdx.x * 64;

    sbias[tid] = bias[tid];

    const uint4* A4 = (const uint4*)A;
    const uint4* B4 = (const uint4*)B;
#pragma unroll
    for (int j = 0; j < 8; j++) {
        int idx = tid + 128 * j;
        int r = idx >> 4, i = idx & 15;
        uint4 v = make_uint4(0, 0, 0, 0);
        if (row0 + r < M) v = A4[(long long)(row0 + r) * 16 + i];
        *(uint4*)(smem + r * MMA_STRIDE + i * 16) = v;
    }
#pragma unroll
    for (int j = 0; j < 16; j++) {
        int idx = tid + 128 * j;
        int r = idx >> 4, i = idx & 15;
        *(uint4*)(smem + SM_B_OFF + r * MMA_STRIDE + i * 16) = B4[idx];
    }
    __syncthreads();

    uint32_t sA = smem_u32(smem);
    uint32_t sB = sA + SM_B_OFF;
    uint32_t aAddr = sA + (wid * 16 + (lane & 15)) * MMA_STRIDE + (lane >> 4) * 16;
    uint32_t bAddr = sB + (lane & 15) * MMA_STRIDE + (lane >> 4) * 16;

    float acc[16][4];
#pragma unroll
    for (int i = 0; i < 16; i++) {
        acc[i][0] = 0.f; acc[i][1] = 0.f; acc[i][2] = 0.f; acc[i][3] = 0.f;
    }

#pragma unroll
    for (int k0 = 0; k0 < DIM; k0 += 16) {
        uint32_t af[4];
        ldsm4(af, aAddr + k0 * 2);
#pragma unroll
        for (int p = 0; p < 8; p++) {
            uint32_t bf[4];
            ldsm4t(bf, bAddr + k0 * MMA_STRIDE + p * 32);
            mma16816(acc[2 * p],     af, bf[0], bf[1]);
            mma16816(acc[2 * p + 1], af, bf[2], bf[3]);
        }
    }

    int rowA = row0 + wid * 16 + gid;
    int rowB = rowA + 8;
    bool vA = rowA < M, vB = rowB < M;

    if (mode == 0) {
#pragma unroll
        for (int nt = 0; nt < 16; nt++) {
            int col = nt * 8 + 2 * tig;
            float b0 = sbias[col], b1 = sbias[col + 1];
            float v0 = fmaxf(acc[nt][0] + b0, 0.f);
            float v1 = fmaxf(acc[nt][1] + b1, 0.f);
            float v2 = fmaxf(acc[nt][2] + b0, 0.f);
            float v3 = fmaxf(acc[nt][3] + b1, 0.f);
            if (vA) *(__half2*)(outh + (long long)rowA * DIM + col) = __floats2half2_rn(v0, v1);
            if (vB) *(__half2*)(outh + (long long)rowB * DIM + col) = __floats2half2_rn(v2, v3);
        }
    } else {
#pragma unroll
        for (int nt = 0; nt < 16; nt++) {
            int col = nt * 8 + 2 * tig;
            float b0 = sbias[col], b1 = sbias[col + 1];
            float v0 = vA ? (acc[nt][0] + b0) : 0.f;
            float v1 = vA ? (acc[nt][1] + b1) : 0.f;
            float v2 = vB ? (acc[nt][2] + b0) : 0.f;
            float v3 = vB ? (acc[nt][3] + b1) : 0.f;
            if (vA) *(float2*)(outf + (long long)rowA * DIM + col) = make_float2(v0, v1);
            if (vB) *(float2*)(outf + (long long)rowB * DIM + col) = make_float2(v2, v3);
            float sE = v0 + v2, qE = v0 * v0 + v2 * v2;
            float sO = v1 + v3, qO = v1 * v1 + v3 * v3;
#pragma unroll
            for (int m = 4; m < 32; m <<= 1) {
                sE += __shfl_xor_sync(0xffffffffu, sE, m);
                qE += __shfl_xor_sync(0xffffffffu, qE, m);
                sO += __shfl_xor_sync(0xffffffffu, sO, m);
                qO += __shfl_xor_sync(0xffffffffu, qO, m);
            }
            if (gid == 0) {
                sS[wid][col] = sE;     sQ[wid][col] = qE;
                sS[wid][col + 1] = sO; sQ[wid][col + 1] = qO;
            }
        }
        __syncthreads();
        float s = sS[0][tid] + sS[1][tid] + sS[2][tid] + sS[3][tid];
        float q = sQ[0][tid] + sQ[1][tid] + sQ[2][tid] + sQ[3][tid];
        atomicAdd(&g_sum[tid], s);
        atomicAdd(&g_sq[tid], q);
    }
}

// ---------------------------------------------------------------------------
// 7) out = h + leaky_relu(z*scale + shift)  (BN fold fused per block)
// ---------------------------------------------------------------------------
__global__ void ewise_kernel(const float* __restrict__ h,
                             const float* __restrict__ Z,
                             const float* __restrict__ gamma,
                             const float* __restrict__ beta,
                             float* __restrict__ out, int total4, float invN) {
    __shared__ float ssc[DIM], ssh[DIM];
    int t = threadIdx.x;
    if (t < DIM) {
        float mean = g_sum[t] * invN;
        float var = g_sq[t] * invN - mean * mean;
        float sc = gamma[t] * rsqrtf(var + 1e-5f);
        ssc[t] = sc;
        ssh[t] = beta[t] - mean * sc;
    }
    __syncthreads();
    int i = blockIdx.x * blockDim.x + t;
    if (i >= total4) return;
    int cg = i & 31;
    float4 sc = ((const float4*)ssc)[cg];
    float4 sh = ((const float4*)ssh)[cg];
    float4 zv = ((const float4*)Z)[i];
    float4 hv = ((const float4*)h)[i];
    float x;
    float4 o;
    x = zv.x * sc.x + sh.x; o.x = hv.x + (x >= 0.f ? x : 0.01f * x);
    x = zv.y * sc.y + sh.y; o.y = hv.y + (x >= 0.f ? x : 0.01f * x);
    x = zv.z * sc.z + sh.z; o.z = hv.z + (x >= 0.f ? x : 0.01f * x);
    x = zv.w * sc.w + sh.w; o.w = hv.w + (x >= 0.f ? x : 0.01f * x);
    ((float4*)out)[i] = o;
}

// ---------------------------------------------------------------------------
extern "C" void kernel_launch(void* const* d_in, const int* in_sizes, int n_in,
                              void* d_out, int out_size) {
    const float* h     = (const float*)d_in[0];
    const int*   src   = (const int*)d_in[1];
    const int*   dst   = (const int*)d_in[2];
    const float* eps   = (const float*)d_in[3];
    const float* W1    = (const float*)d_in[4];
    const float* b1    = (const float*)d_in[5];
    const float* W2    = (const float*)d_in[6];
    const float* b2    = (const float*)d_in[7];
    const float* gamma = (const float*)d_in[8];
    const float* beta  = (const float*)d_in[9];
    float* out = (float*)d_out;

    int N = in_sizes[0] / DIM;
    int E = in_sizes[1];
    int E4 = E / 4;                       // E = 1.6M, divisible by 4
    int total4 = N * (DIM / 4);
    int nblk = (N + SCAN_B - 1) / SCAN_B;

    cudaFuncSetAttribute(mma_kernel,
                         cudaFuncAttributeMaxDynamicSharedMemorySize, SMEM_GEMM);

    void *zp = nullptr, *zhp = nullptr, *yhp = nullptr, *w1p = nullptr, *w2p = nullptr;
    cudaGetSymbolAddress(&zp, g_z);
    cudaGetSymbolAddress(&zhp, g_zh);
    cudaGetSymbolAddress(&yhp, g_yh);
    cudaGetSymbolAddress(&w1p, g_w1h);
    cudaGetSymbolAddress(&w2p, g_w2h);

    int prepwork = (E4 > total4) ? E4 : total4;
    if (prepwork < 2 * DIM * DIM) prepwork = 2 * DIM * DIM;

    // 0-3) build CSR of incoming edges + fp16 conversions
    zero_kernel<<<(N + 255) / 256, 256>>>(N);
    prep_kernel<<<(prepwork + 255) / 256, 256>>>(dst, W1, W2, h, N, E4, total4);
    scan_kernel<<<nblk, SCAN_B>>>(N);
    scatter_kernel<<<(E4 + 255) / 256, 256>>>(src, dst, N, E4);

    // 4) gather (fp16 z out)
    gather_kernel<<<(N * 32 + 255) / 256, 256>>>(h, eps, N);

    // 5) y = relu(z @ W1 + b1)   (fp16 out)
    int gblocks = (N + 63) / 64;
    mma_kernel<<<gblocks, 128, SMEM_GEMM>>>((const __half*)zhp, (const __half*)w1p,
                                            b1, (__half*)yhp, (float*)zp, N, 0);

    // 6) z2 = y @ W2 + b2  (fp32 out + fused BN stats)
    mma_kernel<<<gblocks, 128, SMEM_GEMM>>>((const __half*)yhp, (const __half*)w2p,
                                            b2, (__half*)yhp, (float*)zp, N, 1);

    // 7) out = h + leaky(z2*scale + shift)
    ewise_kernel<<<(total4 + 255) / 256, 256>>>(h, (const float*)zp, gamma, beta,
                                                out, total4, 1.0f / (float)N);
}